// round 14
// baseline (speedup 1.0000x reference)
#include <cuda_runtime.h>

#define W0 0.054488685f
#define W1 0.24420134f
#define W2 0.40261995f

__device__ __forceinline__ int reflect512(int i) {
    i = (i < 0) ? -i : i;
    return (i > 511) ? 1022 - i : i;
}
__device__ __forceinline__ int clamp511(int i) { return min(max(i, 0), 511); }

__device__ __forceinline__ float fast_sqrt(float x) {
    float y = __int_as_float(0x5f3759df - (__float_as_int(x) >> 1));
    y = y * fmaf(-0.5f * x, y * y, 1.5f);
    y = y * fmaf(-0.5f * x, y * y, 1.5f);
    return x * y;
}
__device__ __forceinline__ int octclass(float gx, float gy) {
    const float T = 0.41421356237309503f;  // tan(22.5 deg)
    float ax = fabsf(gx), ay = fabsf(gy);
    if (ay <= T * ax) return 0;
    if (ax <= T * ay) return 2;
    return ((__float_as_int(gx) ^ __float_as_int(gy)) >= 0) ? 1 : 3;
}
__device__ __forceinline__ float g1(float r, float g, float b) {
    return fmaf(0.1495f, r, fmaf(0.2935f, g, fmaf(0.057f, b, 0.5f)));
}

struct BlurRow { float4 v; float mx, my; };   // own 4 cols + margin cols (L: x0-2,x0-1 / R: x0+128,x0+129)
struct MagRow  { float4 v; float l, r;  };    // squared mag, with resolved left/right neighbor cols
struct RawRow  { float4 R, G, B, MR, MG, MB; };

__global__ void __launch_bounds__(64)
canny_stream_kernel(const float* __restrict__ in, float* __restrict__ out)
{
    const int lane  = threadIdx.x & 31;
    const int warp  = threadIdx.x >> 5;
    const int strip = blockIdx.x;                 // 0..3, 128-wide strips
    const int x0    = strip << 7;
    const int xc    = x0 + (lane << 2);           // own cols xc..xc+3
    const int y0    = (blockIdx.y * 2 + warp) << 4;  // 16-row chunk
    const float* base  = in  + (size_t)blockIdx.z * 786432u;
    float*       obase = out + (size_t)blockIdx.z * 262144u;

    const bool eL = (lane == 0), eR = (lane == 31);
    const bool eEdge = eL | eR;
    const bool imgL = eL && (strip == 0);
    const bool imgR = eR && (strip == 3);

    // margin gray columns (4 per side, reflected at image edge)
    int mc0, mc1, mc2, mc3;
    { int b0 = eL ? (x0 - 4) : (x0 + 128);
      mc0 = reflect512(b0); mc1 = reflect512(b0 + 1);
      mc2 = reflect512(b0 + 2); mc3 = reflect512(b0 + 3); }

    float4 hw[5];   // hblur rolling window (rows k-4..k)
    float2 hm[5];   // margin hblur window

    auto load_raw = [&](int k, RawRow& w) {
        int ar = reflect512(k);
        const float* p = base + ar * 512;
        w.R = *(const float4*)(p + xc);
        w.G = *(const float4*)(p + xc + 262144);
        w.B = *(const float4*)(p + xc + 524288);
        if (eEdge) {
            w.MR = make_float4(p[mc0], p[mc1], p[mc2], p[mc3]);
            w.MG = make_float4(p[mc0 + 262144], p[mc1 + 262144], p[mc2 + 262144], p[mc3 + 262144]);
            w.MB = make_float4(p[mc0 + 524288], p[mc1 + 524288], p[mc2 + 524288], p[mc3 + 524288]);
        } else {
            w.MR = w.MG = w.MB = make_float4(0.f, 0.f, 0.f, 0.f);
        }
    };

    auto push = [&](const RawRow& w) {
        float4 g;
        g.x = g1(w.R.x, w.G.x, w.B.x); g.y = g1(w.R.y, w.G.y, w.B.y);
        g.z = g1(w.R.z, w.G.z, w.B.z); g.w = g1(w.R.w, w.G.w, w.B.w);
        float4 gm;
        gm.x = g1(w.MR.x, w.MG.x, w.MB.x); gm.y = g1(w.MR.y, w.MG.y, w.MB.y);
        gm.z = g1(w.MR.z, w.MG.z, w.MB.z); gm.w = g1(w.MR.w, w.MG.w, w.MB.w);
        // horizontal halo via shuffle; edge lanes substitute margins
        float zl = __shfl_up_sync(0xffffffffu, g.z, 1);
        float wl = __shfl_up_sync(0xffffffffu, g.w, 1);
        if (eL) { zl = gm.z; wl = gm.w; }          // cols xc-2, xc-1
        float xr = __shfl_down_sync(0xffffffffu, g.x, 1);
        float yr = __shfl_down_sync(0xffffffffu, g.y, 1);
        if (eR) { xr = gm.x; yr = gm.y; }          // cols xc+4, xc+5
        float4 h;
        h.x = W0 * (zl + g.z)  + W1 * (wl + g.y)  + W2 * g.x;
        h.y = W0 * (wl + g.w)  + W1 * (g.x + g.z) + W2 * g.y;
        h.z = W0 * (g.x + xr)  + W1 * (g.y + g.w) + W2 * g.z;
        h.w = W0 * (g.y + yr)  + W1 * (g.z + xr)  + W2 * g.w;
        // margin hblur: L cols x0-2,x0-1 from {gm.x..gm.w, g.x, g.y};
        //               R cols x0+128,x0+129 from {g.z, g.w, gm.x..gm.w}
        float s0 = eL ? gm.x : g.z,  s1 = eL ? gm.y : g.w,  s2 = eL ? gm.z : gm.x;
        float s3 = eL ? gm.w : gm.y, s4 = eL ? g.x  : gm.z, s5 = eL ? g.y  : gm.w;
        float2 hmm;
        hmm.x = W0 * (s0 + s4) + W1 * (s1 + s3) + W2 * s2;
        hmm.y = W0 * (s1 + s5) + W1 * (s2 + s4) + W2 * s3;
        #pragma unroll
        for (int i = 0; i < 4; i++) { hw[i] = hw[i + 1]; hm[i] = hm[i + 1]; }
        hw[4] = h; hm[4] = hmm;
    };

    auto vblur = [&]() -> BlurRow {
        BlurRow B;
        B.v.x = W0 * (hw[0].x + hw[4].x) + W1 * (hw[1].x + hw[3].x) + W2 * hw[2].x;
        B.v.y = W0 * (hw[0].y + hw[4].y) + W1 * (hw[1].y + hw[3].y) + W2 * hw[2].y;
        B.v.z = W0 * (hw[0].z + hw[4].z) + W1 * (hw[1].z + hw[3].z) + W2 * hw[2].z;
        B.v.w = W0 * (hw[0].w + hw[4].w) + W1 * (hw[1].w + hw[3].w) + W2 * hw[2].w;
        B.mx  = W0 * (hm[0].x + hm[4].x) + W1 * (hm[1].x + hm[3].x) + W2 * hm[2].x;
        B.my  = W0 * (hm[0].y + hm[4].y) + W1 * (hm[1].y + hm[3].y) + W2 * hm[2].y;
        // Sobel edge padding is CLAMP on blurred: at image x-edges the needed
        // out-of-image blur col equals the edge col.
        if (imgL) B.my = B.v.x;    // blur col -1  := blur col 0
        if (imgR) B.mx = B.v.w;    // blur col 512 := blur col 511
        return B;
    };

    // mag row mr from blur rows A(top=mr-1), Bm(mid=mr), C(bot=mr+1), all row-clamped by caller
    auto magrow = [&](const BlurRow& A, const BlurRow& Bq, const BlurRow& C,
                      int mr, MagRow& M, unsigned& cls) {
        float a0 = __shfl_up_sync(0xffffffffu, A.v.w, 1);  if (eL) a0 = A.my;
        float a5 = __shfl_down_sync(0xffffffffu, A.v.x, 1); if (eR) a5 = A.mx;
        float b0 = __shfl_up_sync(0xffffffffu, Bq.v.w, 1); if (eL) b0 = Bq.my;
        float b5 = __shfl_down_sync(0xffffffffu, Bq.v.x, 1); if (eR) b5 = Bq.mx;
        float c0 = __shfl_up_sync(0xffffffffu, C.v.w, 1);  if (eL) c0 = C.my;
        float c5 = __shfl_down_sync(0xffffffffu, C.v.x, 1); if (eR) c5 = C.mx;
        float aa[6] = {a0, A.v.x, A.v.y, A.v.z, A.v.w, a5};
        float bb[6] = {b0, Bq.v.x, Bq.v.y, Bq.v.z, Bq.v.w, b5};
        float cc[6] = {c0, C.v.x, C.v.y, C.v.z, C.v.w, c5};
        float mv[4];
        unsigned cl = 0;
        #pragma unroll
        for (int j = 0; j < 4; j++) {
            float gx = (aa[j+2] - aa[j]) + 2.f * (bb[j+2] - bb[j]) + (cc[j+2] - cc[j]);
            float gy = (cc[j] - aa[j]) + 2.f * (cc[j+1] - aa[j+1]) + (cc[j+2] - aa[j+2]);
            mv[j] = fmaf(gx, gx, fmaf(gy, gy, 1e-6f));
            cl |= (unsigned)octclass(gx, gy) << (8 * j);
        }
        // margin mag: L px col x0-1 uses blur cols (mx,my,v.x); R px col x0+128 uses (v.w,mx,my)
        float t0a = eL ? A.mx  : A.v.w,  t1a = eL ? A.my  : A.mx,  t2a = eL ? A.v.x  : A.my;
        float t0b = eL ? Bq.mx : Bq.v.w,                           t2b = eL ? Bq.v.x : Bq.my;
        float t0c = eL ? C.mx  : C.v.w,  t1c = eL ? C.my  : C.mx,  t2c = eL ? C.v.x  : C.my;
        float gxm = (t2a - t0a) + 2.f * (t2b - t0b) + (t2c - t0c);
        float gym = (t0c - t0a) + 2.f * (t1c - t1a) + (t2c - t2a);
        float mm = fmaf(gxm, gxm, fmaf(gym, gym, 1e-6f));
        float4 m = make_float4(mv[0], mv[1], mv[2], mv[3]);
        float l = __shfl_up_sync(0xffffffffu, m.w, 1);  if (eL) l = mm;
        float r = __shfl_down_sync(0xffffffffu, m.x, 1); if (eR) r = mm;
        if (mr < 0 || mr > 511) { m = make_float4(0.f,0.f,0.f,0.f); l = 0.f; r = 0.f; } // NMS zero-pad rows
        if (imgL) l = 0.f;   // NMS zero-pad cols
        if (imgR) r = 0.f;
        M.v = m; M.l = l; M.r = r; cls = cl;
    };

    // ---------------- prologue ----------------
    int last_ab = clamp511(y0 - 2);
    {   // build hblur window for blur(last_ab): gray rows reflect(last_ab-2 .. last_ab+2)
        RawRow w0r, w1r, w2r, w3r, w4r;
        load_raw(last_ab - 2, w0r); load_raw(last_ab - 1, w1r); load_raw(last_ab, w2r);
        load_raw(last_ab + 1, w3r); load_raw(last_ab + 2, w4r);
        // first push fills; prime window with copies so shifts are harmless
        push(w0r); hw[0]=hw[1]=hw[2]=hw[3]=hw[4]; hm[0]=hm[1]=hm[2]=hm[3]=hm[4];
        push(w1r); push(w2r); push(w3r); push(w4r);
    }
    BlurRow Bn = vblur();
    BlurRow Bp = Bn, Bc = Bn;

    auto advance = [&](int target) {
        Bp = Bc; Bc = Bn;
        if (target != last_ab) {
            RawRow w; load_raw(target + 2, w);
            push(w);
            Bn = vblur();
            last_ab = target;
        }
    };
    auto advance_pre = [&](const RawRow& w, int target) {
        Bp = Bc; Bc = Bn;
        if (target != last_ab) { push(w); Bn = vblur(); last_ab = target; }
    };

    MagRow Mp, Mc, Mn; unsigned Cc, Cn, Cx;
    advance(clamp511(y0 - 1));
    advance(clamp511(y0));
    magrow(Bp, Bc, Bn, y0 - 1, Mp, Cx);
    advance(clamp511(y0 + 1));
    magrow(Bp, Bc, Bn, y0, Mc, Cc);
    advance(clamp511(y0 + 2));
    magrow(Bp, Bc, Bn, y0 + 1, Mn, Cn);

    // ---------------- main loop ----------------
    for (int r = y0; r < y0 + 16; r++) {
        // prefetch gray for the blur row needed this iteration
        int target = clamp511(r + 3);
        RawRow w;
        load_raw(target + 2, w);

        // NMS for row r (squared-magnitude compares: exactly equivalent)
        {
            float pp[6] = {Mp.l, Mp.v.x, Mp.v.y, Mp.v.z, Mp.v.w, Mp.r};
            float cm[6] = {Mc.l, Mc.v.x, Mc.v.y, Mc.v.z, Mc.v.w, Mc.r};
            float nn[6] = {Mn.l, Mn.v.x, Mn.v.y, Mn.v.z, Mn.v.w, Mn.r};
            float rv[4];
            #pragma unroll
            for (int j = 0; j < 4; j++) {
                int c = (int)((Cc >> (8 * j)) & 0xFFu);
                // class -> first neighbor (dy,dx): 0:(0,1) 1:(-1,1) 2:(-1,0) 3:(-1,-1)
                float mp = (c == 0) ? cm[j+2] : (c == 1) ? pp[j+2] : (c == 2) ? pp[j+1] : pp[j];
                float mq = (c == 0) ? cm[j]   : (c == 1) ? nn[j]   : (c == 2) ? nn[j+1] : nn[j+2];
                float m2 = cm[j+1];
                rv[j] = (m2 > mp && m2 > mq) ? fast_sqrt(m2) : 0.0f;
            }
            *(float4*)(obase + r * 512 + xc) = make_float4(rv[0], rv[1], rv[2], rv[3]);
        }

        // advance pipeline: blur(clamp(r+3)) then mag(r+2)
        advance_pre(w, target);
        MagRow Mnew; unsigned Cnew;
        magrow(Bp, Bc, Bn, r + 2, Mnew, Cnew);
        Mp = Mc; Mc = Mn; Mn = Mnew;
        Cc = Cn; Cn = Cnew;
    }
}

extern "C" void kernel_launch(void* const* d_in, const int* in_sizes, int n_in,
                              void* d_out, int out_size)
{
    (void)in_sizes; (void)n_in; (void)out_size;
    const float* data = (const float*)d_in[0];
    float* out = (float*)d_out;

    dim3 grid(4, 16, 16);   // 4 strips x 32 row-chunks (2 warps/CTA) x 16 batches
    dim3 block(64);
    canny_stream_kernel<<<grid, block>>>(data, out);
}

// round 15
// speedup vs baseline: 1.6393x; 1.6393x over previous
#include <cuda_runtime.h>

#define NT 256

__device__ __forceinline__ int reflect512(int i) {
    i = (i < 0) ? -i : i;
    return (i > 511) ? 1022 - i : i;
}
__device__ __forceinline__ int clamp511(int i) { return min(max(i, 0), 511); }
__device__ __forceinline__ float grayf(const float* __restrict__ base, int off) {
    float r = base[off], g = base[off + 262144], b = base[off + 524288];
    return fmaf(0.1495f, r, fmaf(0.2935f, g, fmaf(0.057f, b, 0.5f)));
}
__device__ __forceinline__ int octclass(float gx, float gy) {
    const float T = 0.41421356237309503f;  // tan(22.5 deg)
    float ax = fabsf(gx), ay = fabsf(gy);
    if (ay <= T * ax) return 0;
    if (ax <= T * ay) return 2;
    return ((__float_as_int(gx) ^ __float_as_int(gy)) >= 0) ? 1 : 3;
}
__device__ __forceinline__ float fast_sqrt(float x) {
    float y = __int_as_float(0x5f3759df - (__float_as_int(x) >> 1));
    y = y * fmaf(-0.5f * x, y * y, 1.5f);
    y = y * fmaf(-0.5f * x, y * y, 1.5f);
    return x * y;
}
// pack 2-bit class into LSBs of fp32 squared magnitude (~1e-7 relative noise)
__device__ __forceinline__ float packcls(float m, int c) {
    return __uint_as_float((__float_as_uint(m) & ~3u) | (unsigned)c);
}
__device__ __forceinline__ float4 hblur4(float4 v0, float4 v1,
                                         float w0, float w1, float w2) {
    float4 o;
    o.x = w0 * (v0.x + v1.x) + w1 * (v0.y + v0.w) + w2 * v0.z;
    o.y = w0 * (v0.y + v1.y) + w1 * (v0.z + v1.x) + w2 * v0.w;
    o.z = w0 * (v0.z + v1.z) + w1 * (v0.w + v1.y) + w2 * v1.x;
    o.w = w0 * (v0.w + v1.w) + w1 * (v1.x + v1.z) + w2 * v1.y;
    return o;
}

struct Row6 { float m, x, y, z, w, p; };

__device__ __forceinline__ void sobel_row(const Row6& a, const Row6& b, const Row6& c,
                                          float4& mg) {
    {
        float gx = (a.y - a.m) + 2.0f * (b.y - b.m) + (c.y - c.m);
        float gy = (c.m - a.m) + 2.0f * (c.x - a.x) + (c.y - a.y);
        mg.x = packcls(fmaf(gx, gx, fmaf(gy, gy, 1e-6f)), octclass(gx, gy));
    }
    {
        float gx = (a.z - a.x) + 2.0f * (b.z - b.x) + (c.z - c.x);
        float gy = (c.x - a.x) + 2.0f * (c.y - a.y) + (c.z - a.z);
        mg.y = packcls(fmaf(gx, gx, fmaf(gy, gy, 1e-6f)), octclass(gx, gy));
    }
    {
        float gx = (a.w - a.y) + 2.0f * (b.w - b.y) + (c.w - c.y);
        float gy = (c.y - a.y) + 2.0f * (c.z - a.z) + (c.w - a.w);
        mg.z = packcls(fmaf(gx, gx, fmaf(gy, gy, 1e-6f)), octclass(gx, gy));
    }
    {
        float gx = (a.p - a.z) + 2.0f * (b.p - b.z) + (c.p - c.z);
        float gy = (c.z - a.z) + 2.0f * (c.w - a.w) + (c.p - a.p);
        mg.w = packcls(fmaf(gx, gx, fmaf(gy, gy, 1e-6f)), octclass(gx, gy));
    }
}

__global__ __launch_bounds__(NT)
void canny_fused_kernel(const float* __restrict__ in, float* __restrict__ out)
{
    // CTA = two independent 64x32 sub-tiles sharing barriers (2x ILP between barriers).
    // Per sub-tile: poolA: sg[40][72] -> sb[36][72] ; poolB: th[40][72] -> smg[34][72]
    // (class packed into mag LSBs; no scl buffer).  Static smem = 46080 B.
    __shared__ __align__(16) float poolA[2][40 * 72];
    __shared__ __align__(16) float poolB[2][40 * 72];

    const int tid = threadIdx.x;
    const int by0 = blockIdx.y * 32;
    const float* base = in + (size_t)blockIdx.z * 786432u;
    const float w0 = 0.054488685f, w1 = 0.24420134f, w2 = 0.40261995f;

    const bool reflY = (blockIdx.y == 0u) | (blockIdx.y == 15u);

    // ================= stage 1: gray 40x72 per sub-tile =================
    #pragma unroll
    for (int t = 0; t < 2; t++) {
        float (*sg)[72] = reinterpret_cast<float(*)[72]>(poolA[t]);
        const int bx0 = blockIdx.x * 128 + t * 64;
        const bool reflX = (bx0 == 0) || (bx0 == 448);
        if (!(reflX | reflY)) {
            #pragma unroll
            for (int k = 0; k < 2; k++) {
                int u = tid + k * NT;
                if (u < 360) {
                    int pr = u / 18, g = u - pr * 18;
                    int ly = 2 * pr;
                    int off = (by0 - 4 + ly) * 512 + (bx0 - 4) + 4 * g;
                    #pragma unroll
                    for (int rr = 0; rr < 2; rr++) {
                        float4 r  = *(const float4*)(base + off);
                        float4 gg = *(const float4*)(base + off + 262144);
                        float4 bb = *(const float4*)(base + off + 524288);
                        float4 o;
                        o.x = fmaf(0.1495f, r.x, fmaf(0.2935f, gg.x, fmaf(0.057f, bb.x, 0.5f)));
                        o.y = fmaf(0.1495f, r.y, fmaf(0.2935f, gg.y, fmaf(0.057f, bb.y, 0.5f)));
                        o.z = fmaf(0.1495f, r.z, fmaf(0.2935f, gg.z, fmaf(0.057f, bb.z, 0.5f)));
                        o.w = fmaf(0.1495f, r.w, fmaf(0.2935f, gg.w, fmaf(0.057f, bb.w, 0.5f)));
                        *(float4*)&sg[ly + rr][4 * g] = o;
                        off += 512;
                    }
                }
            }
        } else {
            for (int u = tid; u < 40 * 72; u += NT) {
                int ly = u / 72, lx = u - ly * 72;
                int ay = by0 - 4 + ly, ax = bx0 - 4 + lx;
                float g = 0.0f;
                if ((unsigned)ay < 512u && (unsigned)ax < 512u) g = grayf(base, ay * 512 + ax);
                sg[ly][lx] = g;
            }
        }
    }
    __syncthreads();

    // ================= stage 2: hblur -> th cols 0..67 =================
    #pragma unroll
    for (int t = 0; t < 2; t++) {
        float (*sg)[72] = reinterpret_cast<float(*)[72]>(poolA[t]);
        float (*th)[72] = reinterpret_cast<float(*)[72]>(poolB[t]);
        const int bx0 = blockIdx.x * 128 + t * 64;
        const bool reflX = (bx0 == 0) || (bx0 == 448);
        if (!reflX) {
            #pragma unroll
            for (int k = 0; k < 2; k++) {
                int u = tid + k * NT;
                if (u < 340) {
                    int pr = u / 17, g = u - pr * 17;
                    int ly = 2 * pr;
                    float4 a0 = *(const float4*)&sg[ly][4 * g];
                    float4 a1 = *(const float4*)&sg[ly][4 * g + 4];
                    float4 b0 = *(const float4*)&sg[ly + 1][4 * g];
                    float4 b1 = *(const float4*)&sg[ly + 1][4 * g + 4];
                    *(float4*)&th[ly][4 * g]     = hblur4(a0, a1, w0, w1, w2);
                    *(float4*)&th[ly + 1][4 * g] = hblur4(b0, b1, w0, w1, w2);
                }
            }
        } else {
            const int ox = bx0 - 4;
            for (int u = tid; u < 40 * 68; u += NT) {
                int ly = u / 68, j = u - ly * 68;
                int cx = clamp511(bx0 - 2 + j);
                th[ly][j] = w0 * (sg[ly][reflect512(cx - 2) - ox] + sg[ly][reflect512(cx + 2) - ox])
                          + w1 * (sg[ly][reflect512(cx - 1) - ox] + sg[ly][reflect512(cx + 1) - ox])
                          + w2 * sg[ly][reflect512(cx) - ox];
            }
        }
    }
    __syncthreads();

    // ================= stage 3: vblur -> sb rows 0..35 (aliases sg) =================
    #pragma unroll
    for (int t = 0; t < 2; t++) {
        float (*th)[72] = reinterpret_cast<float(*)[72]>(poolB[t]);
        float (*sb)[72] = reinterpret_cast<float(*)[72]>(poolA[t]);
        #pragma unroll
        for (int k = 0; k < 2; k++) {
            int u = tid + k * NT;
            if (u < 306) {
                int pr = u / 17, g = u - pr * 17;
                int i = 2 * pr;
                if (!reflY) {
                    float4 a = *(const float4*)&th[i    ][4 * g];
                    float4 b = *(const float4*)&th[i + 1][4 * g];
                    float4 c = *(const float4*)&th[i + 2][4 * g];
                    float4 d = *(const float4*)&th[i + 3][4 * g];
                    float4 e = *(const float4*)&th[i + 4][4 * g];
                    float4 f = *(const float4*)&th[i + 5][4 * g];
                    float4 o0, o1;
                    o0.x = w0 * (a.x + e.x) + w1 * (b.x + d.x) + w2 * c.x;
                    o0.y = w0 * (a.y + e.y) + w1 * (b.y + d.y) + w2 * c.y;
                    o0.z = w0 * (a.z + e.z) + w1 * (b.z + d.z) + w2 * c.z;
                    o0.w = w0 * (a.w + e.w) + w1 * (b.w + d.w) + w2 * c.w;
                    o1.x = w0 * (b.x + f.x) + w1 * (c.x + e.x) + w2 * d.x;
                    o1.y = w0 * (b.y + f.y) + w1 * (c.y + e.y) + w2 * d.y;
                    o1.z = w0 * (b.z + f.z) + w1 * (c.z + e.z) + w2 * d.z;
                    o1.w = w0 * (b.w + f.w) + w1 * (c.w + e.w) + w2 * d.w;
                    *(float4*)&sb[i][4 * g]     = o0;
                    *(float4*)&sb[i + 1][4 * g] = o1;
                } else {
                    #pragma unroll
                    for (int rr = 0; rr < 2; rr++) {
                        int ir = i + rr;
                        int cy = clamp511(by0 - 2 + ir), oy = by0 - 4;
                        int r0 = reflect512(cy - 2) - oy, r1 = reflect512(cy - 1) - oy;
                        int r2 = reflect512(cy) - oy;
                        int r3 = reflect512(cy + 1) - oy, r4 = reflect512(cy + 2) - oy;
                        float4 a = *(const float4*)&th[r0][4 * g];
                        float4 b = *(const float4*)&th[r1][4 * g];
                        float4 c = *(const float4*)&th[r2][4 * g];
                        float4 d = *(const float4*)&th[r3][4 * g];
                        float4 e = *(const float4*)&th[r4][4 * g];
                        float4 o;
                        o.x = w0 * (a.x + e.x) + w1 * (b.x + d.x) + w2 * c.x;
                        o.y = w0 * (a.y + e.y) + w1 * (b.y + d.y) + w2 * c.y;
                        o.z = w0 * (a.z + e.z) + w1 * (b.z + d.z) + w2 * c.z;
                        o.w = w0 * (a.w + e.w) + w1 * (b.w + d.w) + w2 * c.w;
                        *(float4*)&sb[ir][4 * g] = o;
                    }
                }
            }
        }
    }
    __syncthreads();

    // ========== stage 4: Sobel + squared mag (class in LSBs) -> smg (aliases th) ==========
    #pragma unroll
    for (int t = 0; t < 2; t++) {
        float (*sb)[72]  = reinterpret_cast<float(*)[72]>(poolA[t]);
        float (*smg)[72] = reinterpret_cast<float(*)[72]>(poolB[t]);
        #pragma unroll
        for (int k = 0; k < 2; k++) {
            int u = tid + k * NT;
            if (u < 289) {
                int pr = u / 17, g = u - pr * 17;
                int i = 2 * pr;
                int cm = max(4 * g - 1, 0);
                Row6 r[4];
                #pragma unroll
                for (int rr = 0; rr < 4; rr++) {
                    const float* row = &sb[i + rr][0];
                    float4 v = *(const float4*)&row[4 * g];
                    r[rr].m = row[cm]; r[rr].x = v.x; r[rr].y = v.y;
                    r[rr].z = v.z;     r[rr].w = v.w;
                    r[rr].p = (g < 16) ? row[4 * g + 4] : row[67];  // col 68 unused-safe clamp
                }
                float4 mgA, mgB;
                sobel_row(r[0], r[1], r[2], mgA);
                sobel_row(r[1], r[2], r[3], mgB);
                *(float4*)&smg[i][4 * g]     = mgA;
                *(float4*)&smg[i + 1][4 * g] = mgB;
            }
        }
    }
    __syncthreads();

    // ================= stage 5: NMS on squared magnitudes + fast_sqrt =================
    const unsigned DY = 0x0001u, DX = 0x0122u;

    #pragma unroll
    for (int t = 0; t < 2; t++) {
        float (*smg)[72] = reinterpret_cast<float(*)[72]>(poolB[t]);
        const int bx0 = blockIdx.x * 128 + t * 64;
        const bool reflX = (bx0 == 0) || (bx0 == 448);
        const bool border = reflX | reflY;
        #pragma unroll
        for (int k = 0; k < 2; k++) {
            int u = tid + k * NT;
            int iy = u >> 4, g = u & 15;
            int ii = iy + 1;
            int j0 = 4 * g + 2;

            float2 ca = *(const float2*)&smg[ii][j0];
            float2 cb = *(const float2*)&smg[ii][j0 + 2];
            float mcv[4] = {ca.x, ca.y, cb.x, cb.y};
            int   cls[4] = {(int)(__float_as_uint(ca.x) & 3u), (int)(__float_as_uint(ca.y) & 3u),
                            (int)(__float_as_uint(cb.x) & 3u), (int)(__float_as_uint(cb.y) & 3u)};

            float4 res;
            float* rp = &res.x;
            #pragma unroll
            for (int p = 0; p < 4; p++) {
                int s  = cls[p] * 4;
                int dy = (int)((DY >> s) & 0xFu) - 1;
                int dx = (int)((DX >> s) & 0xFu) - 1;
                int jj = j0 + p;
                float mp = smg[ii + dy][jj + dx];
                float mq = smg[ii - dy][jj - dx];
                if (border) {
                    int ay = by0 + iy, ax = bx0 + 4 * g + p;
                    if (!((unsigned)(ay + dy) < 512u && (unsigned)(ax + dx) < 512u)) mp = 0.0f;
                    if (!((unsigned)(ay - dy) < 512u && (unsigned)(ax - dx) < 512u)) mq = 0.0f;
                }
                float m = mcv[p];
                rp[p] = (m > mp && m > mq) ? fast_sqrt(m) : 0.0f;
            }
            *(float4*)&out[((size_t)blockIdx.z * 512 + by0 + iy) * 512 + bx0 + 4 * g] = res;
        }
    }
}

extern "C" void kernel_launch(void* const* d_in, const int* in_sizes, int n_in,
                              void* d_out, int out_size)
{
    (void)in_sizes; (void)n_in; (void)out_size;
    const float* data = (const float*)d_in[0];
    float* out = (float*)d_out;

    dim3 grid(4, 16, 16);
    dim3 block(NT);
    canny_fused_kernel<<<grid, block>>>(data, out);
}